// round 11
// baseline (speedup 1.0000x reference)
#include <cuda_runtime.h>
#include <cuda_bf16.h>
#include <cstdint>

// ============================================================================
// ModularLinear on GB300 — base-arch build (mma.sync HMMA.16816 bf16, fp32
// acc, 3-term hi/lo split). R11 = R7 (best: 498us) with one lever: 2 CTAs/SM.
// NSTG 4 -> 3 (96 KB smem/CTA) + __launch_bounds__(384, 2) so two CTAs
// co-reside per SM; the second CTA's consumer warps fill the tensor-pipe gaps
// the first CTA leaves during LDSM bursts / barrier waits.
//
//   out[t, b, kk*1024 + o] = sum_i x[t, b, i] * w[sel[b,kk], o, i]
//   16 independent GEMMs of 2048 x 1024 x 1024 (fp32).
// ============================================================================

#define T_DIM   2048
#define B_DIM   8
#define IN_DIM  1024
#define OUT_DIM 1024
#define K_SEL   2

#define TILE_M  128
#define TILE_N  128
#define KC      32                         // K-chunk (fp32 elements)
#define NCHUNK  (IN_DIM / KC)              // 32
#define THREADS 384                        // 256 consumer + 128 producer
#define NSTG    3

// bf16 tile: 128 rows x 32 bf16 (64B rows), SW64-swizzled -> 8KB
#define BF_TILE     (TILE_M * KC * 2)      // 8192
#define STAGE_BYTES (4 * BF_TILE)          // Ah, Al, Bh, Bl = 32768
#define SMEM_TOTAL  (NSTG * STAGE_BYTES)   // 98304  (2 CTAs/SM fit)

// ---------------------------------------------------------------------------
// PTX helpers (base-arch only)
// ---------------------------------------------------------------------------
__device__ __forceinline__ uint32_t smem_u32(const void* p) {
    uint32_t a;
    asm("{ .reg .u64 t; cvta.to.shared.u64 t, %1; cvt.u32.u64 %0, t; }"
        : "=r"(a) : "l"(p));
    return a;
}

#define BAR_SYNC(id)   asm volatile("bar.sync %0, %1;"   :: "r"(id), "n"(THREADS) : "memory")
#define BAR_ARRIVE(id) asm volatile("bar.arrive %0, %1;" :: "r"(id), "n"(THREADS) : "memory")

__device__ __forceinline__ void ldsm4(uint32_t* r, uint32_t addr) {
    asm volatile("ldmatrix.sync.aligned.m8n8.x4.shared.b16 {%0,%1,%2,%3}, [%4];"
                 : "=r"(r[0]), "=r"(r[1]), "=r"(r[2]), "=r"(r[3])
                 : "r"(addr));
}

// D += A * B  (m16n8k16, bf16 in, fp32 acc)
__device__ __forceinline__ void mma16816(float* c, const uint32_t* a,
                                         const uint32_t* b) {
    asm volatile(
        "mma.sync.aligned.m16n8k16.row.col.f32.bf16.bf16.f32 "
        "{%0,%1,%2,%3}, {%4,%5,%6,%7}, {%8,%9}, {%0,%1,%2,%3};"
        : "+f"(c[0]), "+f"(c[1]), "+f"(c[2]), "+f"(c[3])
        : "r"(a[0]), "r"(a[1]), "r"(a[2]), "r"(a[3]),
          "r"(b[0]), "r"(b[1]));
}

// SW64 swizzle for 64B rows (8-row x 64B atom): bits[5:4] ^= bits[8:7]
__device__ __forceinline__ uint32_t sw64(uint32_t bo) {
    return bo ^ ((bo >> 3) & 0x30);
}

// split 8 consecutive fp32 (two uint4) into hi uint4 + lo uint4 (bf16x2 x4)
__device__ __forceinline__ void split_oct(uint4 u0, uint4 u1,
                                          uint4& hi, uint4& lo) {
    hi.x = __byte_perm(u0.x, u0.y, 0x7632);
    hi.y = __byte_perm(u0.z, u0.w, 0x7632);
    hi.z = __byte_perm(u1.x, u1.y, 0x7632);
    hi.w = __byte_perm(u1.z, u1.w, 0x7632);
    float l0 = __uint_as_float(u0.x) - __uint_as_float(u0.x & 0xFFFF0000u);
    float l1 = __uint_as_float(u0.y) - __uint_as_float(u0.y & 0xFFFF0000u);
    float l2 = __uint_as_float(u0.z) - __uint_as_float(u0.z & 0xFFFF0000u);
    float l3 = __uint_as_float(u0.w) - __uint_as_float(u0.w & 0xFFFF0000u);
    float l4 = __uint_as_float(u1.x) - __uint_as_float(u1.x & 0xFFFF0000u);
    float l5 = __uint_as_float(u1.y) - __uint_as_float(u1.y & 0xFFFF0000u);
    float l6 = __uint_as_float(u1.z) - __uint_as_float(u1.z & 0xFFFF0000u);
    float l7 = __uint_as_float(u1.w) - __uint_as_float(u1.w & 0xFFFF0000u);
    __nv_bfloat162 p0 = __float22bfloat162_rn(make_float2(l0, l1));
    __nv_bfloat162 p1 = __float22bfloat162_rn(make_float2(l2, l3));
    __nv_bfloat162 p2 = __float22bfloat162_rn(make_float2(l4, l5));
    __nv_bfloat162 p3 = __float22bfloat162_rn(make_float2(l6, l7));
    lo.x = *reinterpret_cast<uint32_t*>(&p0);
    lo.y = *reinterpret_cast<uint32_t*>(&p1);
    lo.z = *reinterpret_cast<uint32_t*>(&p2);
    lo.w = *reinterpret_cast<uint32_t*>(&p3);
}

// ============================================================================
// Kernel
// ============================================================================
__global__ void __launch_bounds__(THREADS, 2)
modlin_kernel(const float* __restrict__ x, const int* __restrict__ sel,
              const float* __restrict__ w, float* __restrict__ out)
{
    extern __shared__ char smem[];
    const int tid = threadIdx.x;
    const int wid = tid >> 5;
    const int lid = tid & 31;

    const int nt_blk = blockIdx.x;            // 0..7
    const int mt_blk = blockIdx.y;            // 0..15
    const int pi     = blockIdx.z;            // 0..15  (b,k) pair
    const int b  = pi >> 1;
    const int kk = pi & 1;
    const int m0 = mt_blk * TILE_M;
    const int n0 = nt_blk * TILE_N;

    const int e = sel[b * K_SEL + kk];

    const float* Abase = x + (((size_t)m0 * B_DIM + b) << 10);         // row stride B*IN
    const float* Bbase = w + ((((size_t)e << 10) + (size_t)n0) << 10); // row stride IN

    const uint32_t smem_base = smem_u32(smem);

    if (wid >= 8) {
        // ====================== PRODUCER (warps 8-11) =======================
        const int pid = tid - 256;             // 0..127
        int s = 0;
        for (int c = 0; c < NCHUNK; ++c) {
            if (c >= NSTG) BAR_SYNC(4 + s);    // wait stage empty

            const int kbase = c * KC;
            char* st = smem + s * STAGE_BYTES;

            // 1024 octs per chunk: p 0..3 -> A tile, p 4..7 -> B tile
            uint4 v[16];
            #pragma unroll
            for (int p = 0; p < 8; ++p) {
                int g = pid + p * 128;
                const float* src;
                if (p < 4) {
                    int row = g >> 2, oct = g & 3;
                    src = Abase + (size_t)row * (B_DIM * IN_DIM) + kbase + oct * 8;
                } else {
                    int g2 = g - 512;
                    int row = g2 >> 2, oct = g2 & 3;
                    src = Bbase + (size_t)row * IN_DIM + kbase + oct * 8;
                }
                v[2 * p]     = *reinterpret_cast<const uint4*>(src);
                v[2 * p + 1] = *reinterpret_cast<const uint4*>(src + 4);
            }
            #pragma unroll
            for (int p = 0; p < 8; ++p) {
                int g = pid + p * 128;
                int g2 = (p < 4) ? g : g - 512;
                int row = g2 >> 2, oct = g2 & 3;
                uint4 hi, lo;
                split_oct(v[2 * p], v[2 * p + 1], hi, lo);
                uint32_t sw = sw64((uint32_t)(row * 64 + oct * 16));
                char* hiT = st + ((p < 4) ? 0 : 2 * BF_TILE);
                *reinterpret_cast<uint4*>(hiT + sw) = hi;
                *reinterpret_cast<uint4*>(hiT + BF_TILE + sw) = lo;
            }
            BAR_ARRIVE(1 + s);                 // stage full
            if (++s == NSTG) s = 0;
        }
        return;
    }

    // ======================== CONSUMER (warps 0-7) ==========================
    const int warp_m = (wid & 3) * 32;         // 4 warps in m
    const int warp_n = (wid >> 2) * 64;        // 2 warps in n
    const int tile = lid >> 3;                 // ldmatrix sub-tile 0..3
    const int trow = lid & 7;
    const int qr = lid >> 2;                   // mma fragment row
    const int qc = lid & 3;

    // ldmatrix relative offsets (swizzle-invariant to tile bases)
    uint32_t aOff[2][2], bOff[4][2];
    #pragma unroll
    for (int mt = 0; mt < 2; ++mt)
        #pragma unroll
        for (int k16 = 0; k16 < 2; ++k16) {
            int row = warp_m + mt * 16 + ((tile & 1) << 3) + trow;
            int kb  = k16 * 32 + ((tile >> 1) << 4);
            aOff[mt][k16] = sw64((uint32_t)(row * 64 + kb));
        }
    #pragma unroll
    for (int nt2 = 0; nt2 < 4; ++nt2)
        #pragma unroll
        for (int k16 = 0; k16 < 2; ++k16) {
            int row = warp_n + nt2 * 16 + ((tile >> 1) << 3) + trow;
            int kb  = k16 * 32 + ((tile & 1) << 4);
            bOff[nt2][k16] = sw64((uint32_t)(row * 64 + kb));
        }

    float acc[2][8][4];
    #pragma unroll
    for (int i = 0; i < 2; ++i)
        #pragma unroll
        for (int j = 0; j < 8; ++j)
            #pragma unroll
            for (int v = 0; v < 4; ++v) acc[i][j][v] = 0.0f;

    int s = 0;
    for (int c = 0; c < NCHUNK; ++c) {
        BAR_SYNC(1 + s);                       // wait stage full

        const uint32_t bfB = smem_base + s * STAGE_BYTES;
        const uint32_t ahB = bfB;
        const uint32_t alB = bfB + BF_TILE;
        const uint32_t bhB = bfB + 2 * BF_TILE;
        const uint32_t blB = bfB + 3 * BF_TILE;

        #pragma unroll
        for (int k16 = 0; k16 < 2; ++k16) {
            uint32_t ah[2][4], al[2][4], bh[8][2], bl[8][2];
            #pragma unroll
            for (int mt = 0; mt < 2; ++mt) {
                ldsm4(ah[mt], ahB + aOff[mt][k16]);
                ldsm4(al[mt], alB + aOff[mt][k16]);
            }
            #pragma unroll
            for (int nt2 = 0; nt2 < 4; ++nt2) {
                uint32_t r[4];
                ldsm4(r, bhB + bOff[nt2][k16]);
                bh[2 * nt2][0] = r[0]; bh[2 * nt2][1] = r[1];
                bh[2 * nt2 + 1][0] = r[2]; bh[2 * nt2 + 1][1] = r[3];
                ldsm4(r, blB + bOff[nt2][k16]);
                bl[2 * nt2][0] = r[0]; bl[2 * nt2][1] = r[1];
                bl[2 * nt2 + 1][0] = r[2]; bl[2 * nt2 + 1][1] = r[3];
            }
            // 3-term split: hh + hl + lh (16 independent accs between reuses)
            #pragma unroll
            for (int mt = 0; mt < 2; ++mt)
                #pragma unroll
                for (int nt = 0; nt < 8; ++nt)
                    mma16816(acc[mt][nt], ah[mt], bh[nt]);
            #pragma unroll
            for (int mt = 0; mt < 2; ++mt)
                #pragma unroll
                for (int nt = 0; nt < 8; ++nt)
                    mma16816(acc[mt][nt], ah[mt], bl[nt]);
            #pragma unroll
            for (int mt = 0; mt < 2; ++mt)
                #pragma unroll
                for (int nt = 0; nt < 8; ++nt)
                    mma16816(acc[mt][nt], al[mt], bh[nt]);
        }
        BAR_ARRIVE(4 + s);                     // stage empty
        if (++s == NSTG) s = 0;
    }

    // ---- epilogue: direct fp32 stores ----
    const size_t row_stride = (size_t)B_DIM * K_SEL * OUT_DIM;   // 16384 floats
    #pragma unroll
    for (int mt = 0; mt < 2; ++mt) {
        const int t = m0 + warp_m + mt * 16 + qr;
        float* orow = out + (size_t)t * row_stride
                          + ((size_t)b * K_SEL + kk) * OUT_DIM
                          + n0 + warp_n + qc * 2;
        #pragma unroll
        for (int nt = 0; nt < 8; ++nt) {
            float2 v0 = make_float2(acc[mt][nt][0], acc[mt][nt][1]);
            float2 v1 = make_float2(acc[mt][nt][2], acc[mt][nt][3]);
            *reinterpret_cast<float2*>(orow + nt * 8) = v0;
            *reinterpret_cast<float2*>(orow + nt * 8 + 8 * row_stride) = v1;
        }
    }
}

// ============================================================================
// Launch
// ============================================================================
extern "C" void kernel_launch(void* const* d_in, const int* in_sizes, int n_in,
                              void* d_out, int out_size) {
    (void)in_sizes; (void)n_in; (void)out_size;
    const float* x   = (const float*)d_in[0];
    const int*   sel = (const int*)d_in[1];
    const float* w   = (const float*)d_in[2];
    float*       out = (float*)d_out;

    cudaFuncSetAttribute(modlin_kernel,
                         cudaFuncAttributeMaxDynamicSharedMemorySize, SMEM_TOTAL);

    dim3 grid(OUT_DIM / TILE_N,            // 8
              T_DIM / TILE_M,              // 16
              B_DIM * K_SEL);              // 16
    modlin_kernel<<<grid, THREADS, SMEM_TOTAL>>>(x, sel, w, out);
}

// round 12
// speedup vs baseline: 2.5413x; 2.5413x over previous
#include <cuda_runtime.h>
#include <cuda_fp16.h>
#include <cstdint>

// ============================================================================
// ModularLinear on GB300 — base-arch build. R12: 2-term fp16 split.
//   C = (ah + al) * fp16(b);  dropped term a*(b - fp16(b)) ~ 2e-4 rel.
// R8 skeleton (best passing: 494us): TILE 128x128, KC=64, NSTG=3, 384 thr
// (256 consumer + 128 producer), warp-specialized ring with named barriers.
// MMA count is 2/3 of the 3-term bf16 version; B tile halves.
//
//   out[t, b, kk*1024 + o] = sum_i x[t, b, i] * w[sel[b,kk], o, i]
//   16 independent GEMMs of 2048 x 1024 x 1024 (fp32).
// ============================================================================

#define T_DIM   2048
#define B_DIM   8
#define IN_DIM  1024
#define OUT_DIM 1024
#define K_SEL   2

#define TILE_M  128
#define TILE_N  128
#define KC      64                         // K-chunk (fp32 elements)
#define NCHUNK  (IN_DIM / KC)              // 16
#define THREADS 384                        // 256 consumer + 128 producer
#define NSTG    3

// fp16 tiles: 128 rows x 64 fp16 (128B rows), SW128-swizzled -> 16KB each
#define F_TILE      (TILE_M * KC * 2)      // 16384
#define OFF_AH      0
#define OFF_AL      F_TILE                 // 16384
#define OFF_BH      (2 * F_TILE)           // 32768
#define STAGE_BYTES (3 * F_TILE)           // 49152
#define SMEM_TOTAL  (NSTG * STAGE_BYTES)   // 147456

// ---------------------------------------------------------------------------
// PTX helpers (base-arch only)
// ---------------------------------------------------------------------------
__device__ __forceinline__ uint32_t smem_u32(const void* p) {
    uint32_t a;
    asm("{ .reg .u64 t; cvta.to.shared.u64 t, %1; cvt.u32.u64 %0, t; }"
        : "=r"(a) : "l"(p));
    return a;
}

#define BAR_SYNC(id)   asm volatile("bar.sync %0, %1;"   :: "r"(id), "n"(THREADS) : "memory")
#define BAR_ARRIVE(id) asm volatile("bar.arrive %0, %1;" :: "r"(id), "n"(THREADS) : "memory")

__device__ __forceinline__ void ldsm4(uint32_t* r, uint32_t addr) {
    asm volatile("ldmatrix.sync.aligned.m8n8.x4.shared.b16 {%0,%1,%2,%3}, [%4];"
                 : "=r"(r[0]), "=r"(r[1]), "=r"(r[2]), "=r"(r[3])
                 : "r"(addr));
}

// D += A * B  (m16n8k16, fp16 in, fp32 acc)
__device__ __forceinline__ void mma16816(float* c, const uint32_t* a,
                                         const uint32_t* b) {
    asm volatile(
        "mma.sync.aligned.m16n8k16.row.col.f32.f16.f16.f32 "
        "{%0,%1,%2,%3}, {%4,%5,%6,%7}, {%8,%9}, {%0,%1,%2,%3};"
        : "+f"(c[0]), "+f"(c[1]), "+f"(c[2]), "+f"(c[3])
        : "r"(a[0]), "r"(a[1]), "r"(a[2]), "r"(a[3]),
          "r"(b[0]), "r"(b[1]));
}

// SW128 swizzle for 128B rows: bits[6:4] ^= bits[9:7]
__device__ __forceinline__ uint32_t sw128(uint32_t bo) {
    return bo ^ ((bo >> 3) & 0x70);
}

__device__ __forceinline__ uint32_t f2h2(float a, float b) {
    __half2 h = __floats2half2_rn(a, b);
    return *reinterpret_cast<uint32_t*>(&h);
}

// split 8 fp32 into fp16 hi (uint4) + fp16 lo residual (uint4)
__device__ __forceinline__ void split_oct_f16(uint4 u0, uint4 u1,
                                              uint4& hi, uint4& lo) {
    float f0 = __uint_as_float(u0.x), f1 = __uint_as_float(u0.y);
    float f2 = __uint_as_float(u0.z), f3 = __uint_as_float(u0.w);
    float f4 = __uint_as_float(u1.x), f5 = __uint_as_float(u1.y);
    float f6 = __uint_as_float(u1.z), f7 = __uint_as_float(u1.w);
    __half2 h01 = __floats2half2_rn(f0, f1);
    __half2 h23 = __floats2half2_rn(f2, f3);
    __half2 h45 = __floats2half2_rn(f4, f5);
    __half2 h67 = __floats2half2_rn(f6, f7);
    hi.x = *reinterpret_cast<uint32_t*>(&h01);
    hi.y = *reinterpret_cast<uint32_t*>(&h23);
    hi.z = *reinterpret_cast<uint32_t*>(&h45);
    hi.w = *reinterpret_cast<uint32_t*>(&h67);
    float2 g01 = __half22float2(h01);
    float2 g23 = __half22float2(h23);
    float2 g45 = __half22float2(h45);
    float2 g67 = __half22float2(h67);
    lo.x = f2h2(f0 - g01.x, f1 - g01.y);
    lo.y = f2h2(f2 - g23.x, f3 - g23.y);
    lo.z = f2h2(f4 - g45.x, f5 - g45.y);
    lo.w = f2h2(f6 - g67.x, f7 - g67.y);
}

// convert 8 fp32 to fp16 (rounded) only
__device__ __forceinline__ uint4 cvt_oct_f16(uint4 u0, uint4 u1) {
    uint4 hi;
    hi.x = f2h2(__uint_as_float(u0.x), __uint_as_float(u0.y));
    hi.y = f2h2(__uint_as_float(u0.z), __uint_as_float(u0.w));
    hi.z = f2h2(__uint_as_float(u1.x), __uint_as_float(u1.y));
    hi.w = f2h2(__uint_as_float(u1.z), __uint_as_float(u1.w));
    return hi;
}

// ============================================================================
// Kernel
// ============================================================================
__global__ void __launch_bounds__(THREADS, 1)
modlin_kernel(const float* __restrict__ x, const int* __restrict__ sel,
              const float* __restrict__ w, float* __restrict__ out)
{
    extern __shared__ char smem[];
    const int tid = threadIdx.x;
    const int wid = tid >> 5;
    const int lid = tid & 31;

    const int nt_blk = blockIdx.x;            // 0..7
    const int mt_blk = blockIdx.y;            // 0..15
    const int pi     = blockIdx.z;            // 0..15  (b,k) pair
    const int b  = pi >> 1;
    const int kk = pi & 1;
    const int m0 = mt_blk * TILE_M;
    const int n0 = nt_blk * TILE_N;

    const int e = sel[b * K_SEL + kk];

    const float* Abase = x + (((size_t)m0 * B_DIM + b) << 10);         // row stride B*IN
    const float* Bbase = w + ((((size_t)e << 10) + (size_t)n0) << 10); // row stride IN

    const uint32_t smem_base = smem_u32(smem);

    if (wid >= 8) {
        // ====================== PRODUCER (warps 8-11) =======================
        const int pid = tid - 256;             // 0..127
        int s = 0;
        for (int c = 0; c < NCHUNK; ++c) {
            if (c >= NSTG) BAR_SYNC(4 + s);    // wait stage empty

            const int kbase = c * KC;
            char* st = smem + s * STAGE_BYTES;

            // A: 128 rows x 64 el = 1024 octs -> 8/thread; split hi/lo
            #pragma unroll
            for (int p = 0; p < 8; ++p) {
                int g = pid + p * 128;
                int row = g >> 3, oct = g & 7;
                const float* src =
                    Abase + (size_t)row * (B_DIM * IN_DIM) + kbase + oct * 8;
                uint4 v0 = *reinterpret_cast<const uint4*>(src);
                uint4 v1 = *reinterpret_cast<const uint4*>(src + 4);
                uint4 hi, lo;
                split_oct_f16(v0, v1, hi, lo);
                uint32_t sw = sw128((uint32_t)(row * 128 + oct * 16));
                *reinterpret_cast<uint4*>(st + OFF_AH + sw) = hi;
                *reinterpret_cast<uint4*>(st + OFF_AL + sw) = lo;
            }
            // B: 128 rows x 64 el = 1024 octs -> 8/thread; fp16 round only
            #pragma unroll
            for (int p = 0; p < 8; ++p) {
                int g = pid + p * 128;
                int row = g >> 3, oct = g & 7;
                const float* src =
                    Bbase + (size_t)row * IN_DIM + kbase + oct * 8;
                uint4 v0 = *reinterpret_cast<const uint4*>(src);
                uint4 v1 = *reinterpret_cast<const uint4*>(src + 4);
                uint4 hi = cvt_oct_f16(v0, v1);
                uint32_t sw = sw128((uint32_t)(row * 128 + oct * 16));
                *reinterpret_cast<uint4*>(st + OFF_BH + sw) = hi;
            }
            BAR_ARRIVE(1 + s);                 // stage full
            if (++s == NSTG) s = 0;
        }
        return;
    }

    // ======================== CONSUMER (warps 0-7) ==========================
    // 4 (m) x 2 (n) warp layout; warp tile 32 x 64 (proven geometry)
    const int warp_m = (wid & 3) * 32;
    const int warp_n = (wid >> 2) * 64;
    const int tile = lid >> 3;                 // ldmatrix sub-tile 0..3
    const int trow = lid & 7;
    const int qr = lid >> 2;                   // mma fragment row
    const int qc = lid & 3;

    // ldsm base offsets; k16 variant = base ^ (k16<<5).
    // Identity: sw128(row*128+kb) = row*128 + (kb ^ ((row&7)<<4)) for kb<128.
    uint32_t aBase[2], bBase[4];
    #pragma unroll
    for (int mt = 0; mt < 2; ++mt) {
        int row  = warp_m + mt * 16 + ((tile & 1) << 3) + trow;
        int tsel = (tile >> 1) << 4;
        aBase[mt] = (uint32_t)(row * 128 + (tsel ^ ((row & 7) << 4)));
    }
    #pragma unroll
    for (int nt2 = 0; nt2 < 4; ++nt2) {
        int row  = warp_n + nt2 * 16 + ((tile >> 1) << 3) + trow;
        int tsel = (tile & 1) << 4;
        bBase[nt2] = (uint32_t)(row * 128 + (tsel ^ ((row & 7) << 4)));
    }

    float acc[2][8][4];
    #pragma unroll
    for (int i = 0; i < 2; ++i)
        #pragma unroll
        for (int j = 0; j < 8; ++j)
            #pragma unroll
            for (int v = 0; v < 4; ++v) acc[i][j][v] = 0.0f;

    int s = 0;
    for (int c = 0; c < NCHUNK; ++c) {
        BAR_SYNC(1 + s);                       // wait stage full

        const uint32_t stB = smem_base + s * STAGE_BYTES;
        const uint32_t ahB = stB + OFF_AH;
        const uint32_t alB = stB + OFF_AL;
        const uint32_t bhB = stB + OFF_BH;

        #pragma unroll
        for (int k16 = 0; k16 < 4; ++k16) {
            const uint32_t kx = (uint32_t)(k16 << 5);
            uint32_t ah[2][4], al[2][4], bh[8][2];

            // hi fragments -> hh MMAs
            #pragma unroll
            for (int mt = 0; mt < 2; ++mt)
                ldsm4(ah[mt], ahB + (aBase[mt] ^ kx));
            #pragma unroll
            for (int nt2 = 0; nt2 < 4; ++nt2) {
                uint32_t r[4];
                ldsm4(r, bhB + (bBase[nt2] ^ kx));
                bh[2 * nt2][0] = r[0]; bh[2 * nt2][1] = r[1];
                bh[2 * nt2 + 1][0] = r[2]; bh[2 * nt2 + 1][1] = r[3];
            }
            #pragma unroll
            for (int mt = 0; mt < 2; ++mt)
                #pragma unroll
                for (int nt = 0; nt < 8; ++nt)
                    mma16816(acc[mt][nt], ah[mt], bh[nt]);

            // lo-A fragments -> lh MMAs
            #pragma unroll
            for (int mt = 0; mt < 2; ++mt)
                ldsm4(al[mt], alB + (aBase[mt] ^ kx));
            // last smem read of this stage -> release early
            if (k16 == 3) BAR_ARRIVE(4 + s);
            #pragma unroll
            for (int mt = 0; mt < 2; ++mt)
                #pragma unroll
                for (int nt = 0; nt < 8; ++nt)
                    mma16816(acc[mt][nt], al[mt], bh[nt]);
        }
        if (++s == NSTG) s = 0;
    }

    // ---- epilogue: direct fp32 stores ----
    const size_t row_stride = (size_t)B_DIM * K_SEL * OUT_DIM;   // 16384 floats
    #pragma unroll
    for (int mt = 0; mt < 2; ++mt) {
        const int t = m0 + warp_m + mt * 16 + qr;
        float* orow = out + (size_t)t * row_stride
                          + ((size_t)b * K_SEL + kk) * OUT_DIM
                          + n0 + warp_n + qc * 2;
        #pragma unroll
        for (int nt = 0; nt < 8; ++nt) {
            float2 v0 = make_float2(acc[mt][nt][0], acc[mt][nt][1]);
            float2 v1 = make_float2(acc[mt][nt][2], acc[mt][nt][3]);
            *reinterpret_cast<float2*>(orow + nt * 8) = v0;
            *reinterpret_cast<float2*>(orow + nt * 8 + 8 * row_stride) = v1;
        }
    }
}

// ============================================================================
// Launch
// ============================================================================
extern "C" void kernel_launch(void* const* d_in, const int* in_sizes, int n_in,
                              void* d_out, int out_size) {
    (void)in_sizes; (void)n_in; (void)out_size;
    const float* x   = (const float*)d_in[0];
    const int*   sel = (const int*)d_in[1];
    const float* w   = (const float*)d_in[2];
    float*       out = (float*)d_out;

    cudaFuncSetAttribute(modlin_kernel,
                         cudaFuncAttributeMaxDynamicSharedMemorySize, SMEM_TOTAL);

    dim3 grid(OUT_DIM / TILE_N,            // 8
              T_DIM / TILE_M,              // 16
              B_DIM * K_SEL);              // 16
    modlin_kernel<<<grid, THREADS, SMEM_TOTAL>>>(x, sel, w, out);
}